// round 13
// baseline (speedup 1.0000x reference)
#include <cuda_runtime.h>
#include <cstdint>

// ----------------------------------------------------------------------------
// RBF: K[i,j] = exp(-inv * (||x_i||^2 - 2 x_i.y_j + ||y_j||^2)), 8192x8192x128.
// Adaptive two-phase, 512 threads/CTA (16 warps, warp tile 32x32, 2 CTAs/SM):
//   phase 1: bf16 m16n8k16 HMMA dot estimate, 4 cp.async commit groups with
//   staged waits. If the CTA's whole 128x128 tile provably underflows fp32
//   exp (rigorous bf16 error bound), stream zeros and exit.
//   phase 2 (rare): zero acc, full 3-pass tf32 Ootomo GEMM + exp epilogue.
// ----------------------------------------------------------------------------

#define NR 8192
#define DD 128
#define NSTAGE2 8             // phase-2 k stages of 16
#define P2_STAGE 32768        // Ahi | Alo | Bhi | Blo
#define SMEM_TOTAL 65536      // phase 1: A bf16 32K | B bf16 32K

__device__ float g_x2[NR];
__device__ float g_y2[NR];
// bf16 permuted, chunk-major: uint4 idx = chunk*(NR*4) + row*4 + q
__device__ uint4 g_Xb[NR * 16];
__device__ uint4 g_Yb[NR * 16];
// tf32 hi/lo, stage-major permuted (phase 2): idx = stage*(NR*16) + row*16 + off
__device__ float g_Xhi[NR * DD];
__device__ float g_Xlo[NR * DD];
__device__ float g_Yhi[NR * DD];
__device__ float g_Ylo[NR * DD];

__device__ __forceinline__ void split1(float x, float& h, float& l) {
    uint32_t u;
    asm("cvt.rna.tf32.f32 %0, %1;" : "=r"(u) : "f"(x));
    h = __uint_as_float(u);
    float r = x - h;
    asm("cvt.rna.tf32.f32 %0, %1;" : "=r"(u) : "f"(r));
    l = __uint_as_float(u);
}
__device__ __forceinline__ uint32_t pack_bf16(float lo, float hi) {
    uint32_t r;
    asm("cvt.rn.bf16x2.f32 %0, %1, %2;" : "=r"(r) : "f"(hi), "f"(lo));
    return r;
}
__device__ __forceinline__ void mma16(float* c, uint32_t a0, uint32_t a1,
                                      uint32_t a2, uint32_t a3,
                                      uint32_t b0, uint32_t b1) {
    asm volatile(
        "mma.sync.aligned.m16n8k16.row.col.f32.bf16.bf16.f32 "
        "{%0,%1,%2,%3}, {%4,%5,%6,%7}, {%8,%9}, {%0,%1,%2,%3};"
        : "+f"(c[0]), "+f"(c[1]), "+f"(c[2]), "+f"(c[3])
        : "r"(a0), "r"(a1), "r"(a2), "r"(a3), "r"(b0), "r"(b1));
}
__device__ __forceinline__ void mma8(float* c, float a0, float a1, float a2, float a3,
                                     float b0, float b1) {
    asm volatile(
        "mma.sync.aligned.m16n8k8.row.col.f32.tf32.tf32.f32 "
        "{%0,%1,%2,%3}, {%4,%5,%6,%7}, {%8,%9}, {%0,%1,%2,%3};"
        : "+f"(c[0]), "+f"(c[1]), "+f"(c[2]), "+f"(c[3])
        : "r"(__float_as_uint(a0)), "r"(__float_as_uint(a1)),
          "r"(__float_as_uint(a2)), "r"(__float_as_uint(a3)),
          "r"(__float_as_uint(b0)), "r"(__float_as_uint(b1)));
}
__device__ __forceinline__ void cp16(uint32_t dst, const void* src) {
    asm volatile("cp.async.cg.shared.global [%0], [%1], 16;"
                 :: "r"(dst), "l"(src) : "memory");
}

// ---- prep: one warp per row -------------------------------------------------
__global__ void prep_kernel(const float* __restrict__ X,
                            const float* __restrict__ Y,
                            int nX, int nY) {
    int warp = (blockIdx.x * blockDim.x + threadIdx.x) >> 5;
    int lane = threadIdx.x & 31;
    if (warp >= nX + nY) return;
    const float* src;
    float *dhi, *dlo, *dn;
    uint4* db;
    int row;
    if (warp < nX) { src = X; dhi = g_Xhi; dlo = g_Xlo; dn = g_x2; db = g_Xb; row = warp; }
    else           { src = Y; dhi = g_Yhi; dlo = g_Ylo; dn = g_y2; db = g_Yb; row = warp - nX; }

    // tf32 permuted hi/lo (phase 2 operands)
    const int stg = lane >> 2;
    const int qp = lane & 3;
    const float* r = src + (size_t)row * DD + stg * 16 + qp;
    float v0 = r[0], v1 = r[4], v2 = r[8], v3 = r[12];
    float4 h, l;
    split1(v0, h.x, l.x);
    split1(v1, h.y, l.y);
    split1(v2, h.z, l.z);
    split1(v3, h.w, l.w);
    size_t didx = (size_t)stg * (NR * 16) + (size_t)row * 16 + qp * 4;
    *(float4*)(dhi + didx) = h;
    *(float4*)(dlo + didx) = l;

    // row norm
    float s = v0 * v0 + v1 * v1 + v2 * v2 + v3 * v3;
    #pragma unroll
    for (int o = 16; o > 0; o >>= 1) s += __shfl_xor_sync(0xffffffffu, s, o);
    if (lane == 0) dn[row] = s;

    // bf16 permuted (phase 1 operands): lanes 0..15: chunk c=lane>>2, q=lane&3
    if (lane < 16) {
        const int c = lane >> 2;
        const int qq = lane & 3;
        const float* rr = src + (size_t)row * DD + c * 32;
        uint4 u;
        u.x = pack_bf16(rr[2 * qq],      rr[2 * qq + 1]);
        u.y = pack_bf16(rr[2 * qq + 8],  rr[2 * qq + 9]);
        u.z = pack_bf16(rr[16 + 2 * qq],     rr[16 + 2 * qq + 1]);
        u.w = pack_bf16(rr[16 + 2 * qq + 8], rr[16 + 2 * qq + 9]);
        db[(size_t)c * (NR * 4) + (size_t)row * 4 + qq] = u;
    }
}

// ---- main kernel: 128x128 tile, 16 warps (4m x 4n), warp tile 32x32 --------
__global__ __launch_bounds__(512, 2)
void rbf_mma_kernel(const float* __restrict__ sigma,
                    float* __restrict__ out,
                    int Mtot) {
    extern __shared__ char smem[];
    const int tid = threadIdx.x;
    const int lane = tid & 31;
    const int wid = tid >> 5;       // 0..15
    const int q = lane & 3;
    const int g = lane >> 2;
    const int wm = wid & 3;         // 0..3 (M)
    const int wn = wid >> 2;        // 0..3 (N)

    const int row0 = blockIdx.y * 128;
    const int col0 = blockIdx.x * 128;
    const int rowW = row0 + wm * 32;
    const int colW = col0 + wn * 32;

    // ======================= PHASE 1 FILL (4 cp.async groups) ==============
    // A chunk c -> smem[c*8192 .. +8K); B chunk c -> smem[32768 + c*8192 .. +8K)
    {
        const uint32_t sbase = (uint32_t)__cvta_generic_to_shared(smem);
        const int t8 = tid & 255;
        const bool isA = tid < 256;
        const char* gsrc = (const char*)(isA ? g_Xb + (size_t)row0 * 4
                                             : g_Yb + (size_t)col0 * 4)
                           + (size_t)t8 * 32;
        const uint32_t dbase = sbase + (isA ? 0u : 32768u) + (uint32_t)t8 * 32;
        #pragma unroll
        for (int c = 0; c < 4; c++) {
            const char* s = gsrc + (size_t)c * (NR * 64);
            cp16(dbase + c * 8192, s);
            cp16(dbase + c * 8192 + 16, s + 16);
            asm volatile("cp.async.commit_group;" ::: "memory");
        }
    }

    float acc[2][4][4];
    #pragma unroll
    for (int mt = 0; mt < 2; mt++)
        #pragma unroll
        for (int j = 0; j < 4; j++)
            #pragma unroll
            for (int e = 0; e < 4; e++) acc[mt][j][e] = 0.0f;

    // ======================= PHASE 1 MMA (staged waits) ====================
    const int aOff = (wm * 32 + g) * 64 + q * 16;
    const int bOff = 32768 + (wn * 32 + g) * 64 + q * 16;

    #define CHUNK_MMA(c_)                                                        \
    do {                                                                         \
        const char* ab = smem + (c_) * 8192 + aOff;                              \
        const char* bb = smem + (c_) * 8192 + bOff;                              \
        uint4 A0 = *(const uint4*)(ab);                                          \
        uint4 A1 = *(const uint4*)(ab + 512);                                    \
        uint4 A2 = *(const uint4*)(ab + 1024);                                   \
        uint4 A3 = *(const uint4*)(ab + 1536);                                   \
        _Pragma("unroll")                                                        \
        for (int j = 0; j < 4; j++) {                                            \
            uint4 B = *(const uint4*)(bb + j * 512);                             \
            mma16(acc[0][j], A0.x, A1.x, A0.y, A1.y, B.x, B.y);                  \
            mma16(acc[0][j], A0.z, A1.z, A0.w, A1.w, B.z, B.w);                  \
            mma16(acc[1][j], A2.x, A3.x, A2.y, A3.y, B.x, B.y);                  \
            mma16(acc[1][j], A2.z, A3.z, A2.w, A3.w, B.z, B.w);                  \
        }                                                                        \
    } while (0)

    asm volatile("cp.async.wait_group 3;" ::: "memory");
    __syncthreads();
    CHUNK_MMA(0);
    asm volatile("cp.async.wait_group 2;" ::: "memory");
    __syncthreads();
    CHUNK_MMA(1);
    asm volatile("cp.async.wait_group 1;" ::: "memory");
    __syncthreads();
    CHUNK_MMA(2);
    asm volatile("cp.async.wait_group 0;" ::: "memory");
    __syncthreads();
    CHUNK_MMA(3);
    #undef CHUNK_MMA

    // ======================= DECISION ======================================
    float sv = sigma[0];
    float inv = 1.0f / (sv * sv + 1e-9f);

    // bf16 dot error <= 2^-9*(x2+y2) => 2*err <= 0.004*(x2+y2); margin 0.008.
    // If inv*(2*dot - 0.992*(x2+y2)) < -105 for every element of the tile,
    // exp underflows to exactly 0.0f for both this kernel and the reference.
    int need = 0;
    #pragma unroll
    for (int mt = 0; mt < 2; mt++) {
        const int r0 = rowW + mt * 16 + g;
        const float x2a = g_x2[r0];
        const float x2b = g_x2[r0 + 8];
        #pragma unroll
        for (int j = 0; j < 4; j++) {
            const int cb = colW + j * 8 + 2 * q;
            const float y0 = g_y2[cb];
            const float y1 = g_y2[cb + 1];
            const float* c = acc[mt][j];
            float u0 = inv * (2.0f * c[0] - 0.992f * (x2a + y0));
            float u1 = inv * (2.0f * c[1] - 0.992f * (x2a + y1));
            float u2 = inv * (2.0f * c[2] - 0.992f * (x2b + y0));
            float u3 = inv * (2.0f * c[3] - 0.992f * (x2b + y1));
            float mx = fmaxf(fmaxf(u0, u1), fmaxf(u2, u3));
            need |= (mx >= -105.0f);
        }
    }
    int doit = __syncthreads_or(need);

    if (!doit) {
        // whole tile underflows: fully coalesced streaming zero write
        float4 z = make_float4(0.0f, 0.0f, 0.0f, 0.0f);
        float* dst = out + (size_t)(row0 + wid * 8) * Mtot + col0 + lane * 4;
        #pragma unroll
        for (int r = 0; r < 8; r++)
            __stcs((float4*)(dst + (size_t)r * Mtot), z);
        return;
    }

    // ======================= PHASE 2: full 3-pass tf32 =====================
    #pragma unroll
    for (int mt = 0; mt < 2; mt++)
        #pragma unroll
        for (int j = 0; j < 4; j++)
            #pragma unroll
            for (int e = 0; e < 4; e++) acc[mt][j][e] = 0.0f;

    const int region = tid >> 7;     // 0:Ahi 1:Alo 2:Bhi 3:Blo
    const int t7 = tid & 127;
    const float* gsrc2;
    int gr2;
    if      (region == 0) { gsrc2 = g_Xhi; gr2 = row0; }
    else if (region == 1) { gsrc2 = g_Xlo; gr2 = row0; }
    else if (region == 2) { gsrc2 = g_Yhi; gr2 = col0; }
    else                  { gsrc2 = g_Ylo; gr2 = col0; }
    const float* g2 = gsrc2 + (size_t)(gr2 + t7) * 16;   // this thread's row
    const int soff2 = region * 8192 + t7 * 64;

    {   // prologue: stage 0 -> buf 0 (one row = 4 float4 per thread)
        float4 st[4];
        #pragma unroll
        for (int i = 0; i < 4; i++)
            st[i] = *(const float4*)(g2 + i * 4);
        #pragma unroll
        for (int i = 0; i < 4; i++)
            *(float4*)(smem + soff2 + i * 16) = st[i];
    }
    __syncthreads();

    const int aOff2 = (wm * 32 + g) * 64 + q * 16;
    const int bOff2 = 16384 + (wn * 32 + g) * 64 + q * 16;

    #pragma unroll 2
    for (int s = 0; s < NSTAGE2; s++) {
        char* bs = smem + (s & 1) * P2_STAGE;
        char* bd = smem + ((s + 1) & 1) * P2_STAGE + soff2;
        const float* gn = g2 + (size_t)(s + 1) * (NR * 16);
        const bool pf = (s < NSTAGE2 - 1);

        float4 st[4];
        if (pf) {
            #pragma unroll
            for (int i = 0; i < 4; i++)
                st[i] = *(const float4*)(gn + i * 4);
        }

        // mt-outer to cap register pressure on this (cold) path
        #pragma unroll
        for (int mt = 0; mt < 2; mt++) {
            float4 h0 = *(const float4*)(bs + aOff2 + mt * 1024);
            float4 h1 = *(const float4*)(bs + aOff2 + mt * 1024 + 512);
            float4 l0 = *(const float4*)(bs + aOff2 + 8192 + mt * 1024);
            float4 l1 = *(const float4*)(bs + aOff2 + 8192 + mt * 1024 + 512);
            #pragma unroll
            for (int j = 0; j < 4; j++) {
                float4 bh = *(const float4*)(bs + bOff2 + j * 512);
                float4 bl = *(const float4*)(bs + bOff2 + 8192 + j * 512);
                float* c = acc[mt][j];
                mma8(c, h0.x, h1.x, h0.y, h1.y, bh.x, bh.y);
                mma8(c, h0.x, h1.x, h0.y, h1.y, bl.x, bl.y);
                mma8(c, l0.x, l1.x, l0.y, l1.y, bh.x, bh.y);
                mma8(c, h0.z, h1.z, h0.w, h1.w, bh.z, bh.w);
                mma8(c, h0.z, h1.z, h0.w, h1.w, bl.z, bl.w);
                mma8(c, l0.z, l1.z, l0.w, l1.w, bh.z, bh.w);
            }
        }

        if (pf) {
            #pragma unroll
            for (int i = 0; i < 4; i++)
                *(float4*)(bd + i * 16) = st[i];
        }
        __syncthreads();
    }

    // ======================= EPILOGUE ======================================
    #pragma unroll
    for (int mt = 0; mt < 2; mt++) {
        const int r0 = rowW + mt * 16 + g;
        const float x2a = g_x2[r0];
        const float x2b = g_x2[r0 + 8];
        #pragma unroll
        for (int j = 0; j < 4; j++) {
            const int cb = colW + j * 8 + 2 * q;
            const float y0 = g_y2[cb];
            const float y1 = g_y2[cb + 1];
            const float* c = acc[mt][j];
            float a0 = inv * (2.0f * c[0] - x2a - y0);
            float a1 = inv * (2.0f * c[1] - x2a - y1);
            float a2 = inv * (2.0f * c[2] - x2b - y0);
            float a3 = inv * (2.0f * c[3] - x2b - y1);
            float mx = fmaxf(fmaxf(a0, a1), fmaxf(a2, a3));
            float2 o0, o1;
            if (__any_sync(0xffffffffu, mx > -104.0f)) {
                o0.x = __expf(a0);
                o0.y = __expf(a1);
                o1.x = __expf(a2);
                o1.y = __expf(a3);
            } else {
                o0.x = 0.0f; o0.y = 0.0f; o1.x = 0.0f; o1.y = 0.0f;
            }
            *(float2*)(out + (size_t)r0 * Mtot + cb)       = o0;
            *(float2*)(out + (size_t)(r0 + 8) * Mtot + cb) = o1;
        }
    }
}

// ----------------------------------------------------------------------------
extern "C" void kernel_launch(void* const* d_in, const int* in_sizes, int n_in,
                              void* d_out, int out_size) {
    const float* X = (const float*)d_in[0];
    const float* Y = (const float*)d_in[1];
    const float* sigma = (const float*)d_in[2];
    float* out = (float*)d_out;

    const int D = 128;
    const int n = in_sizes[0] / D;   // 8192
    const int m = in_sizes[1] / D;   // 8192

    cudaFuncSetAttribute(rbf_mma_kernel,
                         cudaFuncAttributeMaxDynamicSharedMemorySize, SMEM_TOTAL);

    {   // bf16 + tf32 hi/lo splits + norms
        int warps = n + m;
        int threads = 256;
        int blocks = (warps * 32 + threads - 1) / threads;
        prep_kernel<<<blocks, threads>>>(X, Y, n, m);
    }

    {   // adaptive HMMA GEMM + exp
        dim3 grid(m / 128, n / 128);
        rbf_mma_kernel<<<grid, 512, SMEM_TOTAL>>>(sigma, out, m);
    }
}

// round 14
// speedup vs baseline: 1.1760x; 1.1760x over previous
#include <cuda_runtime.h>
#include <cstdint>

// ----------------------------------------------------------------------------
// RBF: K[i,j] = exp(-inv * (||x_i||^2 - 2 x_i.y_j + ||y_j||^2)), 8192x8192x128.
// Adaptive two-phase, 128x256 CTA tile = two sequential 128x128 N-tiles
// sharing the A operand (256 threads, 8 warps, warp tile 32x64, 2 CTAs/SM):
//   phase 1: bf16 m16n8k16 HMMA dot estimate. cp.async groups 0-3 = A+B0
//   chunks (staged waits under T0 MMA), groups 4-7 = B1 chunks (stream in
//   under T0 compute/store -> T1 has zero fill wait). Per tile: if the whole
//   128x128 block provably underflows fp32 exp (rigorous bf16 error bound),
//   stream zeros; else run full 3-pass tf32 Ootomo GEMM + exp (rare).
// ----------------------------------------------------------------------------

#define NR 8192
#define DD 128
#define NSTAGE2 8             // phase-2 k stages of 16
#define P2_STAGE 32768        // Ahi | Alo | Bhi | Blo
#define SMEM_TOTAL 98304      // A 32K | B0 32K | B1 32K

__device__ float g_x2[NR];
__device__ float g_y2[NR];
// bf16 permuted, chunk-major: uint4 idx = chunk*(NR*4) + row*4 + q
__device__ uint4 g_Xb[NR * 16];
__device__ uint4 g_Yb[NR * 16];
// tf32 hi/lo, stage-major permuted (phase 2): idx = stage*(NR*16) + row*16 + off
__device__ float g_Xhi[NR * DD];
__device__ float g_Xlo[NR * DD];
__device__ float g_Yhi[NR * DD];
__device__ float g_Ylo[NR * DD];

__device__ __forceinline__ void split1(float x, float& h, float& l) {
    uint32_t u;
    asm("cvt.rna.tf32.f32 %0, %1;" : "=r"(u) : "f"(x));
    h = __uint_as_float(u);
    float r = x - h;
    asm("cvt.rna.tf32.f32 %0, %1;" : "=r"(u) : "f"(r));
    l = __uint_as_float(u);
}
__device__ __forceinline__ uint32_t pack_bf16(float lo, float hi) {
    uint32_t r;
    asm("cvt.rn.bf16x2.f32 %0, %1, %2;" : "=r"(r) : "f"(hi), "f"(lo));
    return r;
}
__device__ __forceinline__ void mma16(float* c, uint32_t a0, uint32_t a1,
                                      uint32_t a2, uint32_t a3,
                                      uint32_t b0, uint32_t b1) {
    asm volatile(
        "mma.sync.aligned.m16n8k16.row.col.f32.bf16.bf16.f32 "
        "{%0,%1,%2,%3}, {%4,%5,%6,%7}, {%8,%9}, {%0,%1,%2,%3};"
        : "+f"(c[0]), "+f"(c[1]), "+f"(c[2]), "+f"(c[3])
        : "r"(a0), "r"(a1), "r"(a2), "r"(a3), "r"(b0), "r"(b1));
}
__device__ __forceinline__ void mma8(float* c, float a0, float a1, float a2, float a3,
                                     float b0, float b1) {
    asm volatile(
        "mma.sync.aligned.m16n8k8.row.col.f32.tf32.tf32.f32 "
        "{%0,%1,%2,%3}, {%4,%5,%6,%7}, {%8,%9}, {%0,%1,%2,%3};"
        : "+f"(c[0]), "+f"(c[1]), "+f"(c[2]), "+f"(c[3])
        : "r"(__float_as_uint(a0)), "r"(__float_as_uint(a1)),
          "r"(__float_as_uint(a2)), "r"(__float_as_uint(a3)),
          "r"(__float_as_uint(b0)), "r"(__float_as_uint(b1)));
}
__device__ __forceinline__ void cp16(uint32_t dst, const void* src) {
    asm volatile("cp.async.cg.shared.global [%0], [%1], 16;"
                 :: "r"(dst), "l"(src) : "memory");
}

// ---- prep: one warp per row -------------------------------------------------
__global__ void prep_kernel(const float* __restrict__ X,
                            const float* __restrict__ Y,
                            int nX, int nY) {
    int warp = (blockIdx.x * blockDim.x + threadIdx.x) >> 5;
    int lane = threadIdx.x & 31;
    if (warp >= nX + nY) return;
    const float* src;
    float *dhi, *dlo, *dn;
    uint4* db;
    int row;
    if (warp < nX) { src = X; dhi = g_Xhi; dlo = g_Xlo; dn = g_x2; db = g_Xb; row = warp; }
    else           { src = Y; dhi = g_Yhi; dlo = g_Ylo; dn = g_y2; db = g_Yb; row = warp - nX; }

    // tf32 permuted hi/lo (phase 2 operands)
    const int stg = lane >> 2;
    const int qp = lane & 3;
    const float* r = src + (size_t)row * DD + stg * 16 + qp;
    float v0 = r[0], v1 = r[4], v2 = r[8], v3 = r[12];
    float4 h, l;
    split1(v0, h.x, l.x);
    split1(v1, h.y, l.y);
    split1(v2, h.z, l.z);
    split1(v3, h.w, l.w);
    size_t didx = (size_t)stg * (NR * 16) + (size_t)row * 16 + qp * 4;
    *(float4*)(dhi + didx) = h;
    *(float4*)(dlo + didx) = l;

    // row norm
    float s = v0 * v0 + v1 * v1 + v2 * v2 + v3 * v3;
    #pragma unroll
    for (int o = 16; o > 0; o >>= 1) s += __shfl_xor_sync(0xffffffffu, s, o);
    if (lane == 0) dn[row] = s;

    // bf16 permuted (phase 1 operands): lanes 0..15: chunk c=lane>>2, q=lane&3
    if (lane < 16) {
        const int c = lane >> 2;
        const int qq = lane & 3;
        const float* rr = src + (size_t)row * DD + c * 32;
        uint4 u;
        u.x = pack_bf16(rr[2 * qq],      rr[2 * qq + 1]);
        u.y = pack_bf16(rr[2 * qq + 8],  rr[2 * qq + 9]);
        u.z = pack_bf16(rr[16 + 2 * qq],     rr[16 + 2 * qq + 1]);
        u.w = pack_bf16(rr[16 + 2 * qq + 8], rr[16 + 2 * qq + 9]);
        db[(size_t)c * (NR * 4) + (size_t)row * 4 + qq] = u;
    }
}

// ---- phase-2 slow path (rare): full 3-pass tf32 GEMM + exp for one tile ----
__device__ __noinline__ void phase2_tile(char* smem, float inv,
                                         float* __restrict__ out,
                                         int Mtot, int row0, int colX) {
    const int tid = threadIdx.x;
    const int lane = tid & 31;
    const int wid = tid >> 5;
    const int q = lane & 3;
    const int g = lane >> 2;
    const int wm = wid & 3;
    const int wn = wid >> 2;
    const int rowW = row0 + wm * 32;
    const int colW = colX + wn * 64;

    float acc[2][8][4];
    #pragma unroll
    for (int mt = 0; mt < 2; mt++)
        #pragma unroll
        for (int j = 0; j < 8; j++)
            #pragma unroll
            for (int e = 0; e < 4; e++) acc[mt][j][e] = 0.0f;

    const int region = tid >> 6;
    const int t6 = tid & 63;
    const float* gsrc2;
    int gr2;
    if      (region == 0) { gsrc2 = g_Xhi; gr2 = row0; }
    else if (region == 1) { gsrc2 = g_Xlo; gr2 = row0; }
    else if (region == 2) { gsrc2 = g_Yhi; gr2 = colX; }
    else                  { gsrc2 = g_Ylo; gr2 = colX; }
    const float* g2 = gsrc2 + (size_t)gr2 * 16 + (size_t)t6 * 4;
    const int soff2 = region * 8192 + t6 * 16;

    __syncthreads();
    {   // prologue: stage 0 -> buf 0
        float4 st[8];
        #pragma unroll
        for (int c = 0; c < 8; c++)
            st[c] = *(const float4*)(g2 + (size_t)c * 256);
        #pragma unroll
        for (int c = 0; c < 8; c++)
            *(float4*)(smem + soff2 + c * 1024) = st[c];
    }
    __syncthreads();

    const int aOff2 = (wm * 32 + g) * 64 + q * 16;
    const int bOff2 = 16384 + (wn * 64 + g) * 64 + q * 16;

    #pragma unroll 2
    for (int s = 0; s < NSTAGE2; s++) {
        char* bs = smem + (s & 1) * P2_STAGE;
        char* bd = smem + ((s + 1) & 1) * P2_STAGE + soff2;
        const float* gn = g2 + (size_t)(s + 1) * (NR * 16);
        const bool pf = (s < NSTAGE2 - 1);

        float4 st[4];
        if (pf) {
            #pragma unroll
            for (int c = 0; c < 4; c++)
                st[c] = *(const float4*)(gn + (size_t)c * 256);
        }

        float4 ah[4], al[4];
        #pragma unroll
        for (int r = 0; r < 4; r++) {
            ah[r] = *(const float4*)(bs + aOff2 + r * 512);
            al[r] = *(const float4*)(bs + aOff2 + 8192 + r * 512);
        }

        #define J2(j_)                                                           \
        do {                                                                     \
            float4 bh = *(const float4*)(bs + bOff2 + (j_) * 512);               \
            float4 bl = *(const float4*)(bs + bOff2 + 8192 + (j_) * 512);        \
            float* c0 = acc[0][j_];                                              \
            mma8(c0, ah[0].x, ah[1].x, ah[0].y, ah[1].y, bh.x, bh.y);            \
            mma8(c0, ah[0].x, ah[1].x, ah[0].y, ah[1].y, bl.x, bl.y);            \
            mma8(c0, al[0].x, al[1].x, al[0].y, al[1].y, bh.x, bh.y);            \
            mma8(c0, ah[0].z, ah[1].z, ah[0].w, ah[1].w, bh.z, bh.w);            \
            mma8(c0, ah[0].z, ah[1].z, ah[0].w, ah[1].w, bl.z, bl.w);            \
            mma8(c0, al[0].z, al[1].z, al[0].w, al[1].w, bh.z, bh.w);            \
            float* c1 = acc[1][j_];                                              \
            mma8(c1, ah[2].x, ah[3].x, ah[2].y, ah[3].y, bh.x, bh.y);            \
            mma8(c1, ah[2].x, ah[3].x, ah[2].y, ah[3].y, bl.x, bl.y);            \
            mma8(c1, al[2].x, al[3].x, al[2].y, al[3].y, bh.x, bh.y);            \
            mma8(c1, ah[2].z, ah[3].z, ah[2].w, ah[3].w, bh.z, bh.w);            \
            mma8(c1, ah[2].z, ah[3].z, ah[2].w, ah[3].w, bl.z, bl.w);            \
            mma8(c1, al[2].z, al[3].z, al[2].w, al[3].w, bh.z, bh.w);            \
        } while (0)

        J2(0); J2(1); J2(2); J2(3);
        if (pf) {
            #pragma unroll
            for (int c = 0; c < 4; c++)
                *(float4*)(bd + c * 1024) = st[c];
            #pragma unroll
            for (int c = 0; c < 4; c++)
                st[c] = *(const float4*)(gn + (size_t)(c + 4) * 256);
        }
        J2(4); J2(5); J2(6); J2(7);
        if (pf) {
            #pragma unroll
            for (int c = 0; c < 4; c++)
                *(float4*)(bd + (c + 4) * 1024) = st[c];
        }
        __syncthreads();
        #undef J2
    }

    // epilogue
    #pragma unroll
    for (int mt = 0; mt < 2; mt++) {
        const int r0 = rowW + mt * 16 + g;
        const float x2a = g_x2[r0];
        const float x2b = g_x2[r0 + 8];
        #pragma unroll
        for (int j = 0; j < 8; j++) {
            const int cb = colW + j * 8 + 2 * q;
            const float y0 = g_y2[cb];
            const float y1 = g_y2[cb + 1];
            const float* c = acc[mt][j];
            float a0 = inv * (2.0f * c[0] - x2a - y0);
            float a1 = inv * (2.0f * c[1] - x2a - y1);
            float a2 = inv * (2.0f * c[2] - x2b - y0);
            float a3 = inv * (2.0f * c[3] - x2b - y1);
            float mx = fmaxf(fmaxf(a0, a1), fmaxf(a2, a3));
            float2 o0, o1;
            if (__any_sync(0xffffffffu, mx > -104.0f)) {
                o0.x = __expf(a0);
                o0.y = __expf(a1);
                o1.x = __expf(a2);
                o1.y = __expf(a3);
            } else {
                o0.x = 0.0f; o0.y = 0.0f; o1.x = 0.0f; o1.y = 0.0f;
            }
            *(float2*)(out + (size_t)r0 * Mtot + cb)       = o0;
            *(float2*)(out + (size_t)(r0 + 8) * Mtot + cb) = o1;
        }
    }
}

// ---- main kernel: 128x256 CTA tile (2 N-tiles), 8 warps, warp tile 32x64 ---
__global__ __launch_bounds__(256, 2)
void rbf_mma_kernel(const float* __restrict__ sigma,
                    float* __restrict__ out,
                    int Mtot) {
    extern __shared__ char smem[];
    const int tid = threadIdx.x;
    const int lane = tid & 31;
    const int wid = tid >> 5;
    const int q = lane & 3;
    const int g = lane >> 2;
    const int wm = wid & 3;
    const int wn = wid >> 2;

    const int row0 = blockIdx.y * 128;
    const int col0 = blockIdx.x * 256;
    const int rowW = row0 + wm * 32;

    const uint32_t sbase = (uint32_t)__cvta_generic_to_shared(smem);

    // ==== FILL: groups 0-3 = A+B0 chunk c; groups 4-7 = B1 chunk c =========
    {
        const int t7 = tid & 127;
        const bool isA = tid < 128;
        const char* gAB0 = (const char*)(isA ? g_Xb + (size_t)row0 * 4
                                             : g_Yb + (size_t)col0 * 4)
                           + (size_t)t7 * 64;
        const uint32_t dAB0 = sbase + (isA ? 0u : 32768u) + (uint32_t)t7 * 64;
        #pragma unroll
        for (int c = 0; c < 4; c++) {
            const char* s = gAB0 + (size_t)c * (NR * 64);
            #pragma unroll
            for (int i = 0; i < 4; i++)
                cp16(dAB0 + c * 8192 + i * 16, s + i * 16);
            asm volatile("cp.async.commit_group;" ::: "memory");
        }
        const char* gB1 = (const char*)(g_Yb + (size_t)(col0 + 128) * 4)
                          + (size_t)tid * 32;
        const uint32_t dB1 = sbase + 65536u + (uint32_t)tid * 32;
        #pragma unroll
        for (int c = 0; c < 4; c++) {
            const char* s = gB1 + (size_t)c * (NR * 64);
            cp16(dB1 + c * 8192, s);
            cp16(dB1 + c * 8192 + 16, s + 16);
            asm volatile("cp.async.commit_group;" ::: "memory");
        }
    }

    // preload row norms (shared by both tiles)
    float x2r[2][2];
    #pragma unroll
    for (int mt = 0; mt < 2; mt++) {
        x2r[mt][0] = g_x2[rowW + mt * 16 + g];
        x2r[mt][1] = g_x2[rowW + mt * 16 + g + 8];
    }
    const float sv = sigma[0];
    const float thr = -105.0f * (sv * sv + 1e-9f);   // 2*dot-0.992*(x2+y2) >= thr?
    const float inv = 1.0f / (sv * sv + 1e-9f);

    const int aOff = (wm * 32 + g) * 64 + q * 16;
    const int bWarp = (wn * 64 + g) * 64 + q * 16;

    float acc[2][8][4];

    #define ACC_ZERO()                                                           \
        _Pragma("unroll")                                                        \
        for (int mt = 0; mt < 2; mt++)                                           \
            _Pragma("unroll")                                                    \
            for (int j = 0; j < 8; j++)                                          \
                _Pragma("unroll")                                                \
                for (int e = 0; e < 4; e++) acc[mt][j][e] = 0.0f

    #define CHUNK_MMA(c_, bbase_)                                                \
    do {                                                                         \
        const char* ab = smem + (c_) * 8192 + aOff;                              \
        const char* bb = smem + (bbase_) + (c_) * 8192 + bWarp;                  \
        uint4 A0 = *(const uint4*)(ab);                                          \
        uint4 A1 = *(const uint4*)(ab + 512);                                    \
        uint4 A2 = *(const uint4*)(ab + 1024);                                   \
        uint4 A3 = *(const uint4*)(ab + 1536);                                   \
        _Pragma("unroll")                                                        \
        for (int j = 0; j < 8; j++) {                                            \
            uint4 B = *(const uint4*)(bb + j * 512);                             \
            mma16(acc[0][j], A0.x, A1.x, A0.y, A1.y, B.x, B.y);                  \
            mma16(acc[0][j], A0.z, A1.z, A0.w, A1.w, B.z, B.w);                  \
            mma16(acc[1][j], A2.x, A3.x, A2.y, A3.y, B.x, B.y);                  \
            mma16(acc[1][j], A2.z, A3.z, A2.w, A3.w, B.z, B.w);                  \
        }                                                                        \
    } while (0)

    // per-tile decision: bf16 dot error <= 2^-9*(x2+y2) => margin 0.008.
    #define DECIDE(colX_, need_)                                                 \
    do {                                                                         \
        need_ = 0;                                                               \
        _Pragma("unroll")                                                        \
        for (int mt = 0; mt < 2; mt++) {                                         \
            _Pragma("unroll")                                                    \
            for (int j = 0; j < 8; j++) {                                        \
                const int cb = (colX_) + wn * 64 + j * 8 + 2 * q;                \
                const float y0 = g_y2[cb];                                       \
                const float y1 = g_y2[cb + 1];                                   \
                const float* c = acc[mt][j];                                     \
                float u0 = fmaf(-0.992f, x2r[mt][0] + y0, c[0] + c[0]);          \
                float u1 = fmaf(-0.992f, x2r[mt][0] + y1, c[1] + c[1]);          \
                float u2 = fmaf(-0.992f, x2r[mt][1] + y0, c[2] + c[2]);          \
                float u3 = fmaf(-0.992f, x2r[mt][1] + y1, c[3] + c[3]);          \
                float mx = fmaxf(fmaxf(u0, u1), fmaxf(u2, u3));                  \
                need_ |= (mx >= thr);                                            \
            }                                                                    \
        }                                                                        \
    } while (0)

    #define ZERO_TILE(colX_)                                                     \
    do {                                                                         \
        float4 z = make_float4(0.0f, 0.0f, 0.0f, 0.0f);                          \
        float* dst = out + (size_t)(row0 + wid * 16) * Mtot + (colX_) + lane * 4;\
        _Pragma("unroll")                                                        \
        for (int r = 0; r < 16; r++)                                             \
            __stcs((float4*)(dst + (size_t)r * Mtot), z);                        \
    } while (0)

    // ======================= TILE 0 ========================================
    ACC_ZERO();
    asm volatile("cp.async.wait_group 7;" ::: "memory");
    __syncthreads();
    CHUNK_MMA(0, 32768);
    asm volatile("cp.async.wait_group 6;" ::: "memory");
    __syncthreads();
    CHUNK_MMA(1, 32768);
    asm volatile("cp.async.wait_group 5;" ::: "memory");
    __syncthreads();
    CHUNK_MMA(2, 32768);
    asm volatile("cp.async.wait_group 4;" ::: "memory");
    __syncthreads();
    CHUNK_MMA(3, 32768);

    int need0;
    DECIDE(col0, need0);
    int doit0 = __syncthreads_or(need0);
    if (!doit0) {
        ZERO_TILE(col0);
    } else {
        phase2_tile(smem, inv, out, Mtot, row0, col0);   // clobbers smem[0,64K)
        // refill A (B1 at [64K,96K) untouched): one cp.async group
        const char* gA = (const char*)(g_Xb + (size_t)row0 * 4) + (size_t)tid * 32;
        const uint32_t dA = sbase + (uint32_t)tid * 32;
        #pragma unroll
        for (int c = 0; c < 4; c++) {
            const char* s = gA + (size_t)c * (NR * 64);
            cp16(dA + c * 8192, s);
            cp16(dA + c * 8192 + 16, s + 16);
        }
        asm volatile("cp.async.commit_group;" ::: "memory");
    }

    // ======================= TILE 1 ========================================
    asm volatile("cp.async.wait_group 0;" ::: "memory");
    __syncthreads();

    ACC_ZERO();
    CHUNK_MMA(0, 65536);
    CHUNK_MMA(1, 65536);
    CHUNK_MMA(2, 65536);
    CHUNK_MMA(3, 65536);

    const int col1 = col0 + 128;
    int need1;
    DECIDE(col1, need1);
    int doit1 = __syncthreads_or(need1);
    if (!doit1) {
        ZERO_TILE(col1);
    } else {
        phase2_tile(smem, inv, out, Mtot, row0, col1);
    }

    #undef ACC_ZERO
    #undef CHUNK_MMA
    #undef DECIDE
    #undef ZERO_TILE
}

// ----------------------------------------------------------------------------
extern "C" void kernel_launch(void* const* d_in, const int* in_sizes, int n_in,
                              void* d_out, int out_size) {
    const float* X = (const float*)d_in[0];
    const float* Y = (const float*)d_in[1];
    const float* sigma = (const float*)d_in[2];
    float* out = (float*)d_out;

    const int D = 128;
    const int n = in_sizes[0] / D;   // 8192
    const int m = in_sizes[1] / D;   // 8192

    cudaFuncSetAttribute(rbf_mma_kernel,
                         cudaFuncAttributeMaxDynamicSharedMemorySize, SMEM_TOTAL);

    {   // bf16 + tf32 hi/lo splits + norms
        int warps = n + m;
        int threads = 256;
        int blocks = (warps * 32 + threads - 1) / threads;
        prep_kernel<<<blocks, threads>>>(X, Y, n, m);
    }

    {   // adaptive HMMA GEMM + exp, 128x256 per CTA
        dim3 grid(m / 256, n / 128);
        rbf_mma_kernel<<<grid, 256, SMEM_TOTAL>>>(sigma, out, m);
    }
}

// round 15
// speedup vs baseline: 1.2202x; 1.0376x over previous
#include <cuda_runtime.h>
#include <cstdint>

// ----------------------------------------------------------------------------
// RBF: K[i,j] = exp(-inv * (||x_i||^2 - 2 x_i.y_j + ||y_j||^2)), 8192x8192x128.
// Adaptive two-phase, 128x512 CTA tile = four sequential 128x128 N-tiles
// sharing the A operand (256 threads, 8 warps, warp tile 32x64, 2 CTAs/SM).
// smem: A bf16 32K | Bbuf0 32K | Bbuf1 32K (B tiles ping-pong, prefetched
// one tile ahead). Per tile: bf16 m16n8k16 dot estimate; if the whole
// 128x128 block provably underflows fp32 exp (rigorous bf16 error bound),
// stream zeros; else full 3-pass tf32 Ootomo GEMM + exp (rare; runs in the
// B-buffer smem region, conservative refill mode afterwards).
// ----------------------------------------------------------------------------

#define NR 8192
#define DD 128
#define NSTAGE2 8             // phase-2 k stages of 16
#define P2_STAGE 32768        // Ahi | Alo | Bhi | Blo
#define SMEM_TOTAL 98304      // A 32K | Bbuf0 32K | Bbuf1 32K

__device__ float g_x2[NR];
__device__ float g_y2[NR];
// bf16 permuted, chunk-major: uint4 idx = chunk*(NR*4) + row*4 + q
__device__ uint4 g_Xb[NR * 16];
__device__ uint4 g_Yb[NR * 16];
// tf32 hi/lo, stage-major permuted (phase 2): idx = stage*(NR*16) + row*16 + off
__device__ float g_Xhi[NR * DD];
__device__ float g_Xlo[NR * DD];
__device__ float g_Yhi[NR * DD];
__device__ float g_Ylo[NR * DD];

__device__ __forceinline__ void split1(float x, float& h, float& l) {
    uint32_t u;
    asm("cvt.rna.tf32.f32 %0, %1;" : "=r"(u) : "f"(x));
    h = __uint_as_float(u);
    float r = x - h;
    asm("cvt.rna.tf32.f32 %0, %1;" : "=r"(u) : "f"(r));
    l = __uint_as_float(u);
}
__device__ __forceinline__ uint32_t pack_bf16(float lo, float hi) {
    uint32_t r;
    asm("cvt.rn.bf16x2.f32 %0, %1, %2;" : "=r"(r) : "f"(hi), "f"(lo));
    return r;
}
__device__ __forceinline__ void mma16(float* c, uint32_t a0, uint32_t a1,
                                      uint32_t a2, uint32_t a3,
                                      uint32_t b0, uint32_t b1) {
    asm volatile(
        "mma.sync.aligned.m16n8k16.row.col.f32.bf16.bf16.f32 "
        "{%0,%1,%2,%3}, {%4,%5,%6,%7}, {%8,%9}, {%0,%1,%2,%3};"
        : "+f"(c[0]), "+f"(c[1]), "+f"(c[2]), "+f"(c[3])
        : "r"(a0), "r"(a1), "r"(a2), "r"(a3), "r"(b0), "r"(b1));
}
__device__ __forceinline__ void mma8(float* c, float a0, float a1, float a2, float a3,
                                     float b0, float b1) {
    asm volatile(
        "mma.sync.aligned.m16n8k8.row.col.f32.tf32.tf32.f32 "
        "{%0,%1,%2,%3}, {%4,%5,%6,%7}, {%8,%9}, {%0,%1,%2,%3};"
        : "+f"(c[0]), "+f"(c[1]), "+f"(c[2]), "+f"(c[3])
        : "r"(__float_as_uint(a0)), "r"(__float_as_uint(a1)),
          "r"(__float_as_uint(a2)), "r"(__float_as_uint(a3)),
          "r"(__float_as_uint(b0)), "r"(__float_as_uint(b1)));
}
__device__ __forceinline__ void cp16(uint32_t dst, const void* src) {
    asm volatile("cp.async.cg.shared.global [%0], [%1], 16;"
                 :: "r"(dst), "l"(src) : "memory");
}

// ---- prep: one warp per row -------------------------------------------------
__global__ void prep_kernel(const float* __restrict__ X,
                            const float* __restrict__ Y,
                            int nX, int nY) {
    int warp = (blockIdx.x * blockDim.x + threadIdx.x) >> 5;
    int lane = threadIdx.x & 31;
    if (warp >= nX + nY) return;
    const float* src;
    float *dhi, *dlo, *dn;
    uint4* db;
    int row;
    if (warp < nX) { src = X; dhi = g_Xhi; dlo = g_Xlo; dn = g_x2; db = g_Xb; row = warp; }
    else           { src = Y; dhi = g_Yhi; dlo = g_Ylo; dn = g_y2; db = g_Yb; row = warp - nX; }

    const int stg = lane >> 2;
    const int qp = lane & 3;
    const float* r = src + (size_t)row * DD + stg * 16 + qp;
    float v0 = r[0], v1 = r[4], v2 = r[8], v3 = r[12];
    float4 h, l;
    split1(v0, h.x, l.x);
    split1(v1, h.y, l.y);
    split1(v2, h.z, l.z);
    split1(v3, h.w, l.w);
    size_t didx = (size_t)stg * (NR * 16) + (size_t)row * 16 + qp * 4;
    *(float4*)(dhi + didx) = h;
    *(float4*)(dlo + didx) = l;

    float s = v0 * v0 + v1 * v1 + v2 * v2 + v3 * v3;
    #pragma unroll
    for (int o = 16; o > 0; o >>= 1) s += __shfl_xor_sync(0xffffffffu, s, o);
    if (lane == 0) dn[row] = s;

    if (lane < 16) {
        const int c = lane >> 2;
        const int qq = lane & 3;
        const float* rr = src + (size_t)row * DD + c * 32;
        uint4 u;
        u.x = pack_bf16(rr[2 * qq],      rr[2 * qq + 1]);
        u.y = pack_bf16(rr[2 * qq + 8],  rr[2 * qq + 9]);
        u.z = pack_bf16(rr[16 + 2 * qq],     rr[16 + 2 * qq + 1]);
        u.w = pack_bf16(rr[16 + 2 * qq + 8], rr[16 + 2 * qq + 9]);
        db[(size_t)c * (NR * 4) + (size_t)row * 4 + qq] = u;
    }
}

// ---- phase-2 slow path (rare): full 3-pass tf32 GEMM + exp for one tile ----
// Uses ws[0, 64K) as its double-buffered staging (the two B buffers).
__device__ __noinline__ void phase2_tile(char* ws, float inv,
                                         float* __restrict__ out,
                                         int Mtot, int row0, int colX) {
    const int tid = threadIdx.x;
    const int lane = tid & 31;
    const int wid = tid >> 5;
    const int q = lane & 3;
    const int g = lane >> 2;
    const int wm = wid & 3;
    const int wn = wid >> 2;
    const int rowW = row0 + wm * 32;
    const int colW = colX + wn * 64;

    float acc[2][8][4];
    #pragma unroll
    for (int mt = 0; mt < 2; mt++)
        #pragma unroll
        for (int j = 0; j < 8; j++)
            #pragma unroll
            for (int e = 0; e < 4; e++) acc[mt][j][e] = 0.0f;

    const int region = tid >> 6;
    const int t6 = tid & 63;
    const float* gsrc2;
    int gr2;
    if      (region == 0) { gsrc2 = g_Xhi; gr2 = row0; }
    else if (region == 1) { gsrc2 = g_Xlo; gr2 = row0; }
    else if (region == 2) { gsrc2 = g_Yhi; gr2 = colX; }
    else                  { gsrc2 = g_Ylo; gr2 = colX; }
    const float* g2 = gsrc2 + (size_t)gr2 * 16 + (size_t)t6 * 4;
    const int soff2 = region * 8192 + t6 * 16;

    __syncthreads();
    {   // prologue: stage 0 -> buf 0
        float4 st[8];
        #pragma unroll
        for (int c = 0; c < 8; c++)
            st[c] = *(const float4*)(g2 + (size_t)c * 256);
        #pragma unroll
        for (int c = 0; c < 8; c++)
            *(float4*)(ws + soff2 + c * 1024) = st[c];
    }
    __syncthreads();

    const int aOff2 = (wm * 32 + g) * 64 + q * 16;
    const int bOff2 = 16384 + (wn * 64 + g) * 64 + q * 16;

    #pragma unroll 2
    for (int s = 0; s < NSTAGE2; s++) {
        char* bs = ws + (s & 1) * P2_STAGE;
        char* bd = ws + ((s + 1) & 1) * P2_STAGE + soff2;
        const float* gn = g2 + (size_t)(s + 1) * (NR * 16);
        const bool pf = (s < NSTAGE2 - 1);

        float4 st[4];
        if (pf) {
            #pragma unroll
            for (int c = 0; c < 4; c++)
                st[c] = *(const float4*)(gn + (size_t)c * 256);
        }

        float4 ah[4], al[4];
        #pragma unroll
        for (int r = 0; r < 4; r++) {
            ah[r] = *(const float4*)(bs + aOff2 + r * 512);
            al[r] = *(const float4*)(bs + aOff2 + 8192 + r * 512);
        }

        #define J2(j_)                                                           \
        do {                                                                     \
            float4 bh = *(const float4*)(bs + bOff2 + (j_) * 512);               \
            float4 bl = *(const float4*)(bs + bOff2 + 8192 + (j_) * 512);        \
            float* c0 = acc[0][j_];                                              \
            mma8(c0, ah[0].x, ah[1].x, ah[0].y, ah[1].y, bh.x, bh.y);            \
            mma8(c0, ah[0].x, ah[1].x, ah[0].y, ah[1].y, bl.x, bl.y);            \
            mma8(c0, al[0].x, al[1].x, al[0].y, al[1].y, bh.x, bh.y);            \
            mma8(c0, ah[0].z, ah[1].z, ah[0].w, ah[1].w, bh.z, bh.w);            \
            mma8(c0, ah[0].z, ah[1].z, ah[0].w, ah[1].w, bl.z, bl.w);            \
            mma8(c0, al[0].z, al[1].z, al[0].w, al[1].w, bh.z, bh.w);            \
            float* c1 = acc[1][j_];                                              \
            mma8(c1, ah[2].x, ah[3].x, ah[2].y, ah[3].y, bh.x, bh.y);            \
            mma8(c1, ah[2].x, ah[3].x, ah[2].y, ah[3].y, bl.x, bl.y);            \
            mma8(c1, al[2].x, al[3].x, al[2].y, al[3].y, bh.x, bh.y);            \
            mma8(c1, ah[2].z, ah[3].z, ah[2].w, ah[3].w, bh.z, bh.w);            \
            mma8(c1, ah[2].z, ah[3].z, ah[2].w, ah[3].w, bl.z, bl.w);            \
            mma8(c1, al[2].z, al[3].z, al[2].w, al[3].w, bh.z, bh.w);            \
        } while (0)

        J2(0); J2(1); J2(2); J2(3);
        if (pf) {
            #pragma unroll
            for (int c = 0; c < 4; c++)
                *(float4*)(bd + c * 1024) = st[c];
            #pragma unroll
            for (int c = 0; c < 4; c++)
                st[c] = *(const float4*)(gn + (size_t)(c + 4) * 256);
        }
        J2(4); J2(5); J2(6); J2(7);
        if (pf) {
            #pragma unroll
            for (int c = 0; c < 4; c++)
                *(float4*)(bd + (c + 4) * 1024) = st[c];
        }
        __syncthreads();
        #undef J2
    }

    // epilogue
    #pragma unroll
    for (int mt = 0; mt < 2; mt++) {
        const int r0 = rowW + mt * 16 + g;
        const float x2a = g_x2[r0];
        const float x2b = g_x2[r0 + 8];
        #pragma unroll
        for (int j = 0; j < 8; j++) {
            const int cb = colW + j * 8 + 2 * q;
            const float y0 = g_y2[cb];
            const float y1 = g_y2[cb + 1];
            const float* c = acc[mt][j];
            float a0 = inv * (2.0f * c[0] - x2a - y0);
            float a1 = inv * (2.0f * c[1] - x2a - y1);
            float a2 = inv * (2.0f * c[2] - x2b - y0);
            float a3 = inv * (2.0f * c[3] - x2b - y1);
            float mx = fmaxf(fmaxf(a0, a1), fmaxf(a2, a3));
            float2 o0, o1;
            if (__any_sync(0xffffffffu, mx > -104.0f)) {
                o0.x = __expf(a0);
                o0.y = __expf(a1);
                o1.x = __expf(a2);
                o1.y = __expf(a3);
            } else {
                o0.x = 0.0f; o0.y = 0.0f; o1.x = 0.0f; o1.y = 0.0f;
            }
            *(float2*)(out + (size_t)r0 * Mtot + cb)       = o0;
            *(float2*)(out + (size_t)(r0 + 8) * Mtot + cb) = o1;
        }
    }
}

// ---- main kernel: 128x512 CTA tile (4 N-tiles), 8 warps, warp tile 32x64 ---
__global__ __launch_bounds__(256, 2)
void rbf_mma_kernel(const float* __restrict__ sigma,
                    float* __restrict__ out,
                    int Mtot) {
    extern __shared__ char smem[];
    const int tid = threadIdx.x;
    const int lane = tid & 31;
    const int wid = tid >> 5;
    const int q = lane & 3;
    const int g = lane >> 2;
    const int wm = wid & 3;
    const int wn = wid >> 2;

    const int row0 = blockIdx.y * 128;
    const int col0 = blockIdx.x * 512;
    const int rowW = row0 + wm * 32;

    const uint32_t sbase = (uint32_t)__cvta_generic_to_shared(smem);

    // issue B tile k into Bbuf[k&1] as ONE commit group (32K: 128B/thread)
    #define ISSUE_B(k_)                                                          \
    do {                                                                         \
        const char* gB = (const char*)(g_Yb + (size_t)(col0 + (k_) * 128) * 4)   \
                         + (size_t)tid * 32;                                     \
        const uint32_t dB = sbase + 32768u + (uint32_t)(((k_) & 1) * 32768)      \
                            + (uint32_t)tid * 32;                                \
        _Pragma("unroll")                                                        \
        for (int c = 0; c < 4; c++) {                                            \
            const char* s = gB + (size_t)c * (NR * 64);                          \
            cp16(dB + c * 8192, s);                                              \
            cp16(dB + c * 8192 + 16, s + 16);                                    \
        }                                                                        \
        asm volatile("cp.async.commit_group;" ::: "memory");                     \
    } while (0)

    // ==== upfront fill: groups 0-3 = {A chunk c + B0 chunk c}; group 4 = B1 ==
    {
        const int t7 = tid & 127;
        const bool isA = tid < 128;
        const char* gAB0 = (const char*)(isA ? g_Xb + (size_t)row0 * 4
                                             : g_Yb + (size_t)col0 * 4)
                           + (size_t)t7 * 64;
        const uint32_t dAB0 = sbase + (isA ? 0u : 32768u) + (uint32_t)t7 * 64;
        #pragma unroll
        for (int c = 0; c < 4; c++) {
            const char* s = gAB0 + (size_t)c * (NR * 64);
            #pragma unroll
            for (int i = 0; i < 4; i++)
                cp16(dAB0 + c * 8192 + i * 16, s + i * 16);
            asm volatile("cp.async.commit_group;" ::: "memory");
        }
        ISSUE_B(1);
    }

    // preload row norms (shared by all tiles)
    float x2r[2][2];
    #pragma unroll
    for (int mt = 0; mt < 2; mt++) {
        x2r[mt][0] = g_x2[rowW + mt * 16 + g];
        x2r[mt][1] = g_x2[rowW + mt * 16 + g + 8];
    }
    const float sv = sigma[0];
    const float thr = -105.0f * (sv * sv + 1e-9f);
    const float inv = 1.0f / (sv * sv + 1e-9f);

    const int aOff = (wm * 32 + g) * 64 + q * 16;
    const int bWarp = (wn * 64 + g) * 64 + q * 16;

    float acc[2][8][4];
    bool cons = false;   // conservative mode after any slow tile

    #define ACC_ZERO()                                                           \
        _Pragma("unroll")                                                        \
        for (int mt = 0; mt < 2; mt++)                                           \
            _Pragma("unroll")                                                    \
            for (int j = 0; j < 8; j++)                                          \
                _Pragma("unroll")                                                \
                for (int e = 0; e < 4; e++) acc[mt][j][e] = 0.0f

    #define CHUNK_MMA(c_, bbase_)                                                \
    do {                                                                         \
        const char* ab = smem + (c_) * 8192 + aOff;                              \
        const char* bb = smem + (bbase_) + (c_) * 8192 + bWarp;                  \
        uint4 A0 = *(const uint4*)(ab);                                          \
        uint4 A1 = *(const uint4*)(ab + 512);                                    \
        uint4 A2 = *(const uint4*)(ab + 1024);                                   \
        uint4 A3 = *(const uint4*)(ab + 1536);                                   \
        _Pragma("unroll")                                                        \
        for (int j = 0; j < 8; j++) {                                            \
            uint4 B = *(const uint4*)(bb + j * 512);                             \
            mma16(acc[0][j], A0.x, A1.x, A0.y, A1.y, B.x, B.y);                  \
            mma16(acc[0][j], A0.z, A1.z, A0.w, A1.w, B.z, B.w);                  \
            mma16(acc[1][j], A2.x, A3.x, A2.y, A3.y, B.x, B.y);                  \
            mma16(acc[1][j], A2.z, A3.z, A2.w, A3.w, B.z, B.w);                  \
        }                                                                        \
    } while (0)

    // bf16 dot error <= 2^-9*(x2+y2) => margin 0.008 -> factor 0.992
    #define DECIDE(colX_, need_)                                                 \
    do {                                                                         \
        need_ = 0;                                                               \
        _Pragma("unroll")                                                        \
        for (int mt = 0; mt < 2; mt++) {                                         \
            _Pragma("unroll")                                                    \
            for (int j = 0; j < 8; j++) {                                        \
                const int cb = (colX_) + wn * 64 + j * 8 + 2 * q;                \
                const float y0 = g_y2[cb];                                       \
                const float y1 = g_y2[cb + 1];                                   \
                const float* c = acc[mt][j];                                     \
                float u0 = fmaf(-0.992f, x2r[mt][0] + y0, c[0] + c[0]);          \
                float u1 = fmaf(-0.992f, x2r[mt][0] + y1, c[1] + c[1]);          \
                float u2 = fmaf(-0.992f, x2r[mt][1] + y0, c[2] + c[2]);          \
                float u3 = fmaf(-0.992f, x2r[mt][1] + y1, c[3] + c[3]);          \
                float mx = fmaxf(fmaxf(u0, u1), fmaxf(u2, u3));                  \
                need_ |= (mx >= thr);                                            \
            }                                                                    \
        }                                                                        \
    } while (0)

    #define ZERO_TILE(colX_)                                                     \
    do {                                                                         \
        float4 z = make_float4(0.0f, 0.0f, 0.0f, 0.0f);                          \
        float* dst = out + (size_t)(row0 + wid * 16) * Mtot + (colX_) + lane * 4;\
        _Pragma("unroll")                                                        \
        for (int r = 0; r < 16; r++)                                             \
            __stcs((float4*)(dst + (size_t)r * Mtot), z);                        \
    } while (0)

    // slow-path handler: drain, phase2 in B-buffer region, enter cons mode
    #define SLOW_TILE(colX_)                                                     \
    do {                                                                         \
        asm volatile("cp.async.wait_group 0;" ::: "memory");                     \
        __syncthreads();                                                         \
        phase2_tile(smem + 32768, inv, out, Mtot, row0, (colX_));                \
        cons = true;                                                             \
    } while (0)

    // ======================= TILE 0 (Bbuf0) ================================
    ACC_ZERO();
    asm volatile("cp.async.wait_group 4;" ::: "memory");
    __syncthreads();
    CHUNK_MMA(0, 32768);
    asm volatile("cp.async.wait_group 3;" ::: "memory");
    __syncthreads();
    CHUNK_MMA(1, 32768);
    asm volatile("cp.async.wait_group 2;" ::: "memory");
    __syncthreads();
    CHUNK_MMA(2, 32768);
    asm volatile("cp.async.wait_group 1;" ::: "memory");
    __syncthreads();
    CHUNK_MMA(3, 32768);

    {
        int need;
        DECIDE(col0, need);
        int doit = __syncthreads_or(need);
        if (!doit) ZERO_TILE(col0);
        else       SLOW_TILE(col0);
        if (cons) ISSUE_B(1);      // B1 clobbered by phase2 -> reissue
        else      ISSUE_B(2);      // fast lookahead
    }

    // ======================= TILE 1 (Bbuf1) ================================
    if (cons) { asm volatile("cp.async.wait_group 0;" ::: "memory"); }
    else      { asm volatile("cp.async.wait_group 1;" ::: "memory"); }
    __syncthreads();
    ACC_ZERO();
    CHUNK_MMA(0, 65536);
    CHUNK_MMA(1, 65536);
    CHUNK_MMA(2, 65536);
    CHUNK_MMA(3, 65536);
    {
        const int col1 = col0 + 128;
        int need;
        DECIDE(col1, need);
        int doit = __syncthreads_or(need);
        if (!doit) ZERO_TILE(col1);
        else       SLOW_TILE(col1);
        if (cons) ISSUE_B(2);
        else      ISSUE_B(3);
    }

    // ======================= TILE 2 (Bbuf0) ================================
    if (cons) { asm volatile("cp.async.wait_group 0;" ::: "memory"); }
    else      { asm volatile("cp.async.wait_group 1;" ::: "memory"); }
    __syncthreads();
    ACC_ZERO();
    CHUNK_MMA(0, 32768);
    CHUNK_MMA(1, 32768);
    CHUNK_MMA(2, 32768);
    CHUNK_MMA(3, 32768);
    {
        const int col2 = col0 + 256;
        int need;
        DECIDE(col2, need);
        int doit = __syncthreads_or(need);
        if (!doit) ZERO_TILE(col2);
        else       SLOW_TILE(col2);
        if (cons) ISSUE_B(3);
    }

    // ======================= TILE 3 (Bbuf1) ================================
    asm volatile("cp.async.wait_group 0;" ::: "memory");
    __syncthreads();
    ACC_ZERO();
    CHUNK_MMA(0, 65536);
    CHUNK_MMA(1, 65536);
    CHUNK_MMA(2, 65536);
    CHUNK_MMA(3, 65536);
    {
        const int col3 = col0 + 384;
        int need;
        DECIDE(col3, need);
        int doit = __syncthreads_or(need);
        if (!doit) ZERO_TILE(col3);
        else       SLOW_TILE(col3);
    }

    #undef ACC_ZERO
    #undef CHUNK_MMA
    #undef DECIDE
    #undef ZERO_TILE
    #undef SLOW_TILE
    #undef ISSUE_B
}

// ----------------------------------------------------------------------------
extern "C" void kernel_launch(void* const* d_in, const int* in_sizes, int n_in,
                              void* d_out, int out_size) {
    const float* X = (const float*)d_in[0];
    const float* Y = (const float*)d_in[1];
    const float* sigma = (const float*)d_in[2];
    float* out = (float*)d_out;

    const int D = 128;
    const int n = in_sizes[0] / D;   // 8192
    const int m = in_sizes[1] / D;   // 8192

    cudaFuncSetAttribute(rbf_mma_kernel,
                         cudaFuncAttributeMaxDynamicSharedMemorySize, SMEM_TOTAL);

    {   // bf16 + tf32 hi/lo splits + norms
        int warps = n + m;
        int threads = 256;
        int blocks = (warps * 32 + threads - 1) / threads;
        prep_kernel<<<blocks, threads>>>(X, Y, n, m);
    }

    {   // adaptive HMMA GEMM + exp, 128x512 per CTA
        dim3 grid(m / 512, n / 128);
        rbf_mma_kernel<<<grid, 256, SMEM_TOTAL>>>(sigma, out, m);
    }
}